// round 15
// baseline (speedup 1.0000x reference)
#include <cuda_runtime.h>
#include <cuda_bf16.h>
#include <math.h>
#include <float.h>
#include <stdint.h>

#define BSZ   256
#define MROW  32768
#define DIM   512
#define KNEG  10
#define MARGIN_F 0.1f
#define EPS_F 1e-6f
#define TMARGIN_F 0.31622776601683794f

#define BN 64               // j rows per gemm tile
#define BKC 64              // K per chunk (bf16)
#define NCHUNK (DIM / BKC)  // 8
#define PADK 72             // padded k-stride (144 B), ldsm conflict-free
#define STRB (PADK * 2)

#define NTILE (MROW / BN)   // 512 tiles
#define GRID  (NTILE * 5)   // 2560 blocks: 4 convert + 1 gemm per tile

// dynamic smem (bytes) — R7 layout
#define A_T0   0
#define A_T1   36864            // 256*144
#define B_T0   73728
#define B_T1   82944            // + 64*144
#define NN_OFF 92160            // 64*8 u32 = 2048
#define NNEG_OFF 94208          // 256*10 int = 10240
#define TROW_OFF 104448         // 64 int
#define SMEM_DYN 104704
// epilogue tables overlay stage A_T0
#define T_TH  0
#define T_NA  1024
#define T_SA  2048
#define T_DAP 3072
#define T_NB  4096
#define T_SB  4352

// ---------------- scratch globals ----------------
__device__ float         g_thresh[BSZ];
__device__ float         g_na[BSZ];
__device__ float         g_sa[BSZ];
__device__ float         g_dap[BSZ];
__device__ int           g_nneg[BSZ * KNEG];
__device__ float         g_nb[MROW];
__device__ float         g_sb[MROW];
__device__ __align__(256) __nv_bfloat16 g_Abf[BSZ * DIM];
__device__ __align__(256) __nv_bfloat16 g_Bbf[(size_t)MROW * DIM];
__device__ unsigned      g_cnt[NTILE];
__device__ double        g_total;
__device__ int           g_count;
__device__ unsigned      g_done = 0;

// ---------------- helpers ----------------
__device__ __forceinline__ uint32_t smem_u32(const void* p) {
    uint32_t a;
    asm("{ .reg .u64 t; cvta.to.shared.u64 t, %1; cvt.u32.u64 %0, t; }" : "=r"(a) : "l"(p));
    return a;
}
__device__ __forceinline__ void ldsm_x4(uint32_t* r, uint32_t addr) {
    asm volatile("ldmatrix.sync.aligned.m8n8.x4.shared.b16 {%0,%1,%2,%3}, [%4];"
                 : "=r"(r[0]), "=r"(r[1]), "=r"(r[2]), "=r"(r[3]) : "r"(addr));
}
__device__ __forceinline__ void mma16816(float* d, const uint32_t* a, uint32_t b0, uint32_t b1) {
    asm volatile(
        "mma.sync.aligned.m16n8k16.row.col.f32.bf16.bf16.f32 "
        "{%0,%1,%2,%3}, {%4,%5,%6,%7}, {%8,%9}, {%0,%1,%2,%3};"
        : "+f"(d[0]), "+f"(d[1]), "+f"(d[2]), "+f"(d[3])
        : "r"(a[0]), "r"(a[1]), "r"(a[2]), "r"(a[3]), "r"(b0), "r"(b1));
}
#define CP_ASYNC16(dst, src) \
    asm volatile("cp.async.cg.shared.global [%0], [%1], 16;" :: "r"(dst), "l"(src))
#define CP_COMMIT()  asm volatile("cp.async.commit_group;" ::: "memory")
#define CP_WAIT0()   asm volatile("cp.async.wait_group 0;" ::: "memory")

__inline__ __device__ float warpReduceSum(float v) {
    #pragma unroll
    for (int o = 16; o > 0; o >>= 1) v += __shfl_down_sync(0xffffffffu, v, o);
    return v;
}
__inline__ __device__ int warpReduceSumI(int v) {
    #pragma unroll
    for (int o = 16; o > 0; o >>= 1) v += __shfl_down_sync(0xffffffffu, v, o);
    return v;
}
__device__ __forceinline__ uint32_t packbf(float x, float y) {
    __nv_bfloat162 t = __float22bfloat162_rn(make_float2(x, y));
    return *(uint32_t*)&t;
}

// ---------------- Kernel A: per-query setup + A bf16 convert + flag reset ----------------
__global__ __launch_bounds__(256)
void setup_kernel(const float* __restrict__ col,
                  const float* __restrict__ row,
                  const int* __restrict__ targets_col,
                  const int* __restrict__ qidxs,
                  const int* __restrict__ nnegs) {
    int i = blockIdx.x;
    int tid = threadIdx.x;
    int w = tid >> 5, lid = tid & 31;

    if (i == 0) {                       // reset overlap flags (replay-safe)
        g_cnt[tid] = 0;
        g_cnt[tid + 256] = 0;
    }

    const float* q = col + (size_t)i * DIM;
    const float* p = row + (size_t)(BSZ + i) * DIM;

    float na = 0.f, sa = 0.f, ps = 0.f, dap2 = 0.f;
    #pragma unroll
    for (int t = 0; t < 2; t++) {
        int k = tid + t * 256;
        float qv = q[k], pv = p[k];
        na += qv * qv;
        sa += qv;
        ps += qv * pv;
        float dlt = qv - pv + EPS_F;
        dap2 += dlt * dlt;
        g_Abf[i * DIM + k] = __float2bfloat16_rn(qv);
    }
    __shared__ float sh[4][8];
    na = warpReduceSum(na); sa = warpReduceSum(sa);
    ps = warpReduceSum(ps); dap2 = warpReduceSum(dap2);
    if (lid == 0) { sh[0][w] = na; sh[1][w] = sa; sh[2][w] = ps; sh[3][w] = dap2; }
    __syncthreads();

    if (w == 0) {
        int tc = targets_col[i];
        int qloc = 0, has = 0;
        #pragma unroll
        for (int g = 0; g < 8; g++) {
            int qv = qidxs[g * 32 + lid];
            unsigned word = __ballot_sync(0xffffffffu, qv == tc);
            if (!has && word) { qloc = g * 32 + __ffs(word) - 1; has = 1; }
        }
        if (lid < KNEG) g_nneg[i * KNEG + lid] = nnegs[qloc * KNEG + lid];
        if (lid == 0) {
            float rna = 0.f, rsa = 0.f, rps = 0.f, rdap2 = 0.f;
            #pragma unroll
            for (int k = 0; k < 8; k++) {
                rna += sh[0][k]; rsa += sh[1][k]; rps += sh[2][k]; rdap2 += sh[3][k];
            }
            g_thresh[i] = has ? (rps - MARGIN_F) : FLT_MAX;
            g_na[i] = rna; g_sa[i] = rsa; g_dap[i] = sqrtf(rdap2);
            if (i == 0) { g_total = 0.0; g_count = 0; }
        }
    }
}

// ---------------- Kernel B: mega, interleaved roles per tile ----------------
// bid -> tile = bid/5, role = bid%5. roles 0..3: convert 16 B-rows each.
// role 4: R7 gemm for the tile (waits on g_cnt[tile]==4).
__global__ __launch_bounds__(512, 2)
void mega_kernel(const float* __restrict__ Brow,
                 const int* __restrict__ targets_row,
                 float* __restrict__ out) {
    extern __shared__ char dsm[];
    int tid = threadIdx.x;
    int wid = tid >> 5, lid = tid & 31;
    int bid = blockIdx.x;
    int tile = bid / 5;
    int role = bid - tile * 5;

    // ================= convert role =================
    if (role < 4) {
        int j = tile * BN + role * 16 + wid;   // 16 warps, one row each
        const float4* src = (const float4*)(Brow + (size_t)j * DIM);
        uint2* dst = (uint2*)(g_Bbf + (size_t)j * DIM);
        float nb = 0.f, sb = 0.f;
        #pragma unroll
        for (int t = 0; t < 4; t++) {
            float4 v = src[lid + t * 32];
            nb += v.x*v.x + v.y*v.y + v.z*v.z + v.w*v.w;
            sb += v.x + v.y + v.z + v.w;
            uint2 pk;
            pk.x = packbf(v.x, v.y);
            pk.y = packbf(v.z, v.w);
            dst[lid + t * 32] = pk;
        }
        nb = warpReduceSum(nb);
        sb = warpReduceSum(sb);
        if (lid == 0) { g_nb[j] = nb; g_sb[j] = sb; }
        __threadfence();                 // release: stores visible before flag
        __syncthreads();
        if (tid == 0) atomicAdd(&g_cnt[tile], 1u);
        return;
    }

    // ================= gemm role (R7 mainloop, unchanged) =================
    __shared__ float red_s[16];
    __shared__ int   red_c[16];

    uint32_t sb = smem_u32(dsm);
    int j0 = tile * BN;

    // wait for our 4 convert blocks (release/acquire via g_cnt)
    if (tid == 0) {
        volatile unsigned* vc = (volatile unsigned*)g_cnt;
        while (vc[tile] < 4u) { }
    }
    __syncthreads();
    __threadfence();

    int i0w = (wid >> 1) * 32, j0w = (wid & 1) * 32;

    float acc[2][4][4];
    #pragma unroll
    for (int a = 0; a < 2; a++)
        #pragma unroll
        for (int b = 0; b < 4; b++)
            #pragma unroll
            for (int c = 0; c < 4; c++) acc[a][b][c] = 0.f;

    uint32_t a_lane = (uint32_t)((lid & 15) * STRB + (lid >> 4) * 16);
    uint32_t b_lane = (uint32_t)(((lid & 7) + ((lid >> 4) & 1) * 8) * STRB + ((lid >> 3) & 1) * 16);

    int*      s_nneg = (int*)(dsm + NNEG_OFF);
    int*      s_trow = (int*)(dsm + TROW_OFF);
    unsigned* s_nn   = (unsigned*)(dsm + NN_OFF);

    int arow = tid >> 3, ah = tid & 7;
    const char* Asrc = (const char*)(g_Abf + arow * DIM + ah * 8);
    const char* Bsrc = (const char*)(g_Bbf + (size_t)(j0 + arow) * DIM + ah * 8);
    uint32_t a_sdst = (uint32_t)(arow * STRB + ah * 16);

    // ---- prologue ----
    {
        #pragma unroll
        for (int p = 0; p < 5; p++) s_nneg[tid + p * 512] = g_nneg[tid + p * 512];
        if (tid < BN) s_trow[tid] = targets_row[j0 + tid];

        #pragma unroll
        for (int p = 0; p < 4; p++)
            CP_ASYNC16(sb + A_T0 + a_sdst + p * 64 * STRB, Asrc + (size_t)p * 64 * DIM * 2);
        CP_ASYNC16(sb + B_T0 + a_sdst, Bsrc);
        CP_COMMIT();
        __syncthreads();

        {
            int myneg[KNEG];
            #pragma unroll 1
            for (int g = 0; g < 8; g++) {
                int i = g * 32 + lid;
                #pragma unroll
                for (int k = 0; k < KNEG; k++) myneg[k] = s_nneg[i * KNEG + k];
                #pragma unroll
                for (int r = 0; r < 4; r++) {
                    int rrow = wid * 4 + r;
                    int t = s_trow[rrow];
                    bool m = false;
                    #pragma unroll
                    for (int k = 0; k < KNEG; k++) m = m || (myneg[k] == t);
                    unsigned word = __ballot_sync(0xffffffffu, m);
                    if (lid == 0) s_nn[rrow * 8 + g] = word;
                }
            }
        }
        CP_WAIT0();
        __syncthreads();
    }

    // ---- mainloop ----
    #pragma unroll 1
    for (int kt = 0; kt < NCHUNK; kt++) {
        int buf = kt & 1;
        uint32_t Ab = sb + (buf ? A_T1 : A_T0);
        uint32_t Bb = sb + (buf ? B_T1 : B_T0);

        if (kt < NCHUNK - 1) {
            uint32_t AbN = sb + (buf ? A_T0 : A_T1);
            uint32_t BbN = sb + (buf ? B_T0 : B_T1);
            size_t kc = (size_t)(kt + 1) * BKC * 2;
            #pragma unroll
            for (int p = 0; p < 4; p++)
                CP_ASYNC16(AbN + a_sdst + p * 64 * STRB, Asrc + (size_t)p * 64 * DIM * 2 + kc);
            CP_ASYNC16(BbN + a_sdst, Bsrc + kc);
            CP_COMMIT();
        }

        #pragma unroll
        for (int ks = 0; ks < BKC; ks += 16) {
            uint32_t afr[2][4], bfr[2][4];
            #pragma unroll
            for (int mt = 0; mt < 2; mt++)
                ldsm_x4(afr[mt], Ab + (uint32_t)((i0w + mt * 16) * STRB + ks * 2) + a_lane);
            #pragma unroll
            for (int np = 0; np < 2; np++)
                ldsm_x4(bfr[np], Bb + (uint32_t)((j0w + np * 16) * STRB + ks * 2) + b_lane);
            #pragma unroll
            for (int mt = 0; mt < 2; mt++) {
                #pragma unroll
                for (int np = 0; np < 2; np++) {
                    mma16816(acc[mt][np * 2 + 0], afr[mt], bfr[np][0], bfr[np][1]);
                    mma16816(acc[mt][np * 2 + 1], afr[mt], bfr[np][2], bfr[np][3]);
                }
            }
        }

        if (kt < NCHUNK - 1) CP_WAIT0();
        __syncthreads();
    }

    // ---- epilogue tables (overlay stage A_T0) ----
    float* s_th  = (float*)(dsm + T_TH);
    float* s_na  = (float*)(dsm + T_NA);
    float* s_sa  = (float*)(dsm + T_SA);
    float* s_dap = (float*)(dsm + T_DAP);
    float* s_nb  = (float*)(dsm + T_NB);
    float* s_sb  = (float*)(dsm + T_SB);

    if (tid < 256) {
        s_th[tid]  = g_thresh[tid];
        s_na[tid]  = g_na[tid];
        s_sa[tid]  = g_sa[tid];
        s_dap[tid] = g_dap[tid];
    }
    if (tid < BN) {
        s_nb[tid] = g_nb[j0 + tid];
        s_sb[tid] = g_sb[j0 + tid];
    }
    __syncthreads();

    const float cterm = (float)DIM * EPS_F * EPS_F;
    float sumtl = 0.f;
    int cnt = 0;
    #pragma unroll
    for (int mt = 0; mt < 2; mt++) {
        int i1 = i0w + mt * 16 + (lid >> 2);
        int i2 = i1 + 8;
        float th1 = s_th[i1], na1 = s_na[i1], sa1 = s_sa[i1], dp1 = s_dap[i1];
        float th2 = s_th[i2], na2 = s_na[i2], sa2 = s_sa[i2], dp2 = s_dap[i2];
        int g1 = i1 >> 5, g2 = i2 >> 5;
        unsigned bit1 = 1u << (i1 & 31), bit2 = 1u << (i2 & 31);
        #pragma unroll
        for (int nt = 0; nt < 4; nt++) {
            int jl = j0w + nt * 8 + (lid & 3) * 2;
            #pragma unroll
            for (int c = 0; c < 4; c++) {
                int jj = jl + (c & 1);
                float s = acc[mt][nt][c];
                float th  = (c < 2) ? th1 : th2;
                unsigned bit = (c < 2) ? bit1 : bit2;
                int g = (c < 2) ? g1 : g2;
                if (s > th && !(s_nn[jj * 8 + g] & bit)) {
                    float na = (c < 2) ? na1 : na2;
                    float sa = (c < 2) ? sa1 : sa2;
                    float dp = (c < 2) ? dp1 : dp2;
                    cnt++;
                    float dan2 = na + s_nb[jj] - 2.0f * s
                               + 2.0f * EPS_F * (sa - s_sb[jj]) + cterm;
                    float dan = sqrtf(fmaxf(dan2, 0.0f));
                    float tl = dp - dan + TMARGIN_F;
                    if (tl > 0.0f) sumtl += tl;
                }
            }
        }
    }
    sumtl = warpReduceSum(sumtl);
    cnt   = warpReduceSumI(cnt);
    if (lid == 0) { red_s[wid] = sumtl; red_c[wid] = cnt; }
    __syncthreads();
    if (tid == 0) {
        float ts = 0.f; int tc = 0;
        #pragma unroll
        for (int w = 0; w < 16; w++) { ts += red_s[w]; tc += red_c[w]; }
        if (tc > 0) { atomicAdd(&g_total, (double)ts); atomicAdd(&g_count, tc); }
        __threadfence();
        unsigned d = atomicAdd(&g_done, 1u);
        if (d == NTILE - 1) {
            g_done = 0;
            __threadfence();
            int c = g_count;
            out[0] = (c > 0) ? (float)(g_total / (double)c) : 0.0f;
        }
    }
}

extern "C" void kernel_launch(void* const* d_in, const int* in_sizes, int n_in,
                              void* d_out, int out_size) {
    const float* inputs_col  = (const float*)d_in[0];
    const float* inputs_row  = (const float*)d_in[1];
    const int*   targets_col = (const int*)d_in[2];
    const int*   targets_row = (const int*)d_in[3];
    const int*   qidxs       = (const int*)d_in[4];
    // d_in[5] = pidxs: dead in the reference loss
    const int*   nnegs       = (const int*)d_in[6];

    cudaFuncSetAttribute(mega_kernel, cudaFuncAttributeMaxDynamicSharedMemorySize, SMEM_DYN);

    setup_kernel<<<BSZ, 256>>>(inputs_col, inputs_row, targets_col, qidxs, nnegs);
    mega_kernel<<<GRID, 512, SMEM_DYN>>>(inputs_row, targets_row, (float*)d_out);
}

// round 17
// speedup vs baseline: 1.2577x; 1.2577x over previous
#include <cuda_runtime.h>
#include <cuda_bf16.h>
#include <math.h>
#include <float.h>
#include <stdint.h>

#define BSZ   256
#define MROW  32768
#define DIM   512
#define KNEG  10
#define MARGIN_F 0.1f
#define EPS_F 1e-6f
#define TMARGIN_F 0.31622776601683794f

#define BN 64               // j rows per gemm tile
#define BKC 64              // K per chunk (bf16)
#define NCHUNK (DIM / BKC)  // 8
#define PADK 72             // padded k-stride (144 B), ldsm conflict-free
#define STRB (PADK * 2)

#define NTILE (MROW / BN)   // 512

// dynamic smem (bytes) — R7 layout (NNEG region now unused)
#define A_T0   0
#define A_T1   36864            // 256*144
#define B_T0   73728
#define B_T1   82944            // + 64*144
#define NN_OFF 92160            // 64*8 u32 = 2048
#define SMEM_DYN 104704
// epilogue tables overlay stage A_T0
#define T_TH  0
#define T_NA  1024
#define T_SA  2048
#define T_DAP 3072
#define T_NB  4096
#define T_SB  4352

#define CONV_BLOCKS (MROW / 8)  // 4096

// ---------------- scratch globals ----------------
__device__ float         g_thresh[BSZ];
__device__ float         g_na[BSZ];
__device__ float         g_sa[BSZ];
__device__ float         g_dap[BSZ];
__device__ int           g_nneg[BSZ * KNEG];
__device__ float         g_nb[MROW];
__device__ float         g_sb[MROW];
__device__ unsigned      g_nonneg[(size_t)MROW * 8];
__device__ __align__(256) __nv_bfloat16 g_Abf[BSZ * DIM];
__device__ __align__(256) __nv_bfloat16 g_Bbf[(size_t)MROW * DIM];
__device__ double        g_total;
__device__ int           g_count;
__device__ unsigned      g_done = 0;

// ---------------- helpers ----------------
__device__ __forceinline__ uint32_t smem_u32(const void* p) {
    uint32_t a;
    asm("{ .reg .u64 t; cvta.to.shared.u64 t, %1; cvt.u32.u64 %0, t; }" : "=r"(a) : "l"(p));
    return a;
}
__device__ __forceinline__ void ldsm_x4(uint32_t* r, uint32_t addr) {
    asm volatile("ldmatrix.sync.aligned.m8n8.x4.shared.b16 {%0,%1,%2,%3}, [%4];"
                 : "=r"(r[0]), "=r"(r[1]), "=r"(r[2]), "=r"(r[3]) : "r"(addr));
}
__device__ __forceinline__ void mma16816(float* d, const uint32_t* a, uint32_t b0, uint32_t b1) {
    asm volatile(
        "mma.sync.aligned.m16n8k16.row.col.f32.bf16.bf16.f32 "
        "{%0,%1,%2,%3}, {%4,%5,%6,%7}, {%8,%9}, {%0,%1,%2,%3};"
        : "+f"(d[0]), "+f"(d[1]), "+f"(d[2]), "+f"(d[3])
        : "r"(a[0]), "r"(a[1]), "r"(a[2]), "r"(a[3]), "r"(b0), "r"(b1));
}
#define CP_ASYNC16(dst, src) \
    asm volatile("cp.async.cg.shared.global [%0], [%1], 16;" :: "r"(dst), "l"(src))
#define CP_COMMIT()  asm volatile("cp.async.commit_group;" ::: "memory")
#define CP_WAIT0()   asm volatile("cp.async.wait_group 0;" ::: "memory")

__inline__ __device__ float warpReduceSum(float v) {
    #pragma unroll
    for (int o = 16; o > 0; o >>= 1) v += __shfl_down_sync(0xffffffffu, v, o);
    return v;
}
__inline__ __device__ int warpReduceSumI(int v) {
    #pragma unroll
    for (int o = 16; o > 0; o >>= 1) v += __shfl_down_sync(0xffffffffu, v, o);
    return v;
}
__device__ __forceinline__ uint32_t packbf(float x, float y) {
    __nv_bfloat162 t = __float22bfloat162_rn(make_float2(x, y));
    return *(uint32_t*)&t;
}

// ---------------- Kernel A: prep (B convert + stats | per-query setup) — R7 ----------------
__global__ __launch_bounds__(256)
void prep_kernel(const float* __restrict__ col,
                 const float* __restrict__ row,
                 const int* __restrict__ targets_col,
                 const int* __restrict__ qidxs,
                 const int* __restrict__ nnegs) {
    int bid = blockIdx.x;
    int tid = threadIdx.x;
    int w = tid >> 5, lid = tid & 31;

    if (bid < CONV_BLOCKS) {
        int j = bid * 8 + w;
        const float4* src = (const float4*)(row + (size_t)j * DIM);
        uint2* dst = (uint2*)(g_Bbf + (size_t)j * DIM);
        float nb = 0.f, sb = 0.f;
        #pragma unroll
        for (int t = 0; t < 4; t++) {
            float4 v = src[lid + t * 32];
            nb += v.x*v.x + v.y*v.y + v.z*v.z + v.w*v.w;
            sb += v.x + v.y + v.z + v.w;
            uint2 pk;
            pk.x = packbf(v.x, v.y);
            pk.y = packbf(v.z, v.w);
            dst[lid + t * 32] = pk;
        }
        nb = warpReduceSum(nb);
        sb = warpReduceSum(sb);
        if (lid == 0) { g_nb[j] = nb; g_sb[j] = sb; }
        return;
    }

    int i = bid - CONV_BLOCKS;
    const float* q = col + (size_t)i * DIM;
    const float* p = row + (size_t)(BSZ + i) * DIM;

    float na = 0.f, sa = 0.f, ps = 0.f, dap2 = 0.f;
    #pragma unroll
    for (int t = 0; t < 2; t++) {
        int k = tid + t * 256;
        float qv = q[k], pv = p[k];
        na += qv * qv;
        sa += qv;
        ps += qv * pv;
        float dlt = qv - pv + EPS_F;
        dap2 += dlt * dlt;
        g_Abf[i * DIM + k] = __float2bfloat16_rn(qv);
    }
    __shared__ float sh[4][8];
    na = warpReduceSum(na); sa = warpReduceSum(sa);
    ps = warpReduceSum(ps); dap2 = warpReduceSum(dap2);
    if (lid == 0) { sh[0][w] = na; sh[1][w] = sa; sh[2][w] = ps; sh[3][w] = dap2; }
    __syncthreads();

    if (w == 0) {
        int tc = targets_col[i];
        int qloc = 0, has = 0;
        #pragma unroll
        for (int g = 0; g < 8; g++) {
            int qv = qidxs[g * 32 + lid];
            unsigned word = __ballot_sync(0xffffffffu, qv == tc);
            if (!has && word) { qloc = g * 32 + __ffs(word) - 1; has = 1; }
        }
        if (lid < KNEG) g_nneg[i * KNEG + lid] = nnegs[qloc * KNEG + lid];
        if (lid == 0) {
            float rna = 0.f, rsa = 0.f, rps = 0.f, rdap2 = 0.f;
            #pragma unroll
            for (int k = 0; k < 8; k++) {
                rna += sh[0][k]; rsa += sh[1][k]; rps += sh[2][k]; rdap2 += sh[3][k];
            }
            g_thresh[i] = has ? (rps - MARGIN_F) : FLT_MAX;
            g_na[i] = rna; g_sa[i] = rsa; g_dap[i] = sqrtf(rdap2);
            if (i == 0) { g_total = 0.0; g_count = 0; }
        }
    }
}

// ---------------- Kernel B: nonneg bitmask (one tile per block) ----------------
__global__ __launch_bounds__(256)
void mask_kernel(const int* __restrict__ targets_row) {
    __shared__ int s_nneg[BSZ * KNEG];
    __shared__ int s_trow[BN];
    int tid = threadIdx.x, w = tid >> 5, lid = tid & 31;
    int j0 = blockIdx.x * BN;
    #pragma unroll
    for (int p = 0; p < 10; p++) s_nneg[tid + p * 256] = g_nneg[tid + p * 256];
    if (tid < BN) s_trow[tid] = targets_row[j0 + tid];
    __syncthreads();

    int myneg[KNEG];
    #pragma unroll 1
    for (int g = 0; g < 8; g++) {
        int i = g * 32 + lid;
        #pragma unroll
        for (int k = 0; k < KNEG; k++) myneg[k] = s_nneg[i * KNEG + k];
        #pragma unroll
        for (int r = 0; r < 8; r++) {
            int rrow = w * 8 + r;
            int t = s_trow[rrow];
            bool m = false;
            #pragma unroll
            for (int k = 0; k < KNEG; k++) m = m || (myneg[k] == t);
            unsigned word = __ballot_sync(0xffffffffu, m);
            if (lid == 0) g_nonneg[(size_t)(j0 + rrow) * 8 + g] = word;
        }
    }
}

// ---------------- Kernel C: gemm (R7 mainloop, mask preloaded, hoisted addressing) ----------------
__global__ __launch_bounds__(512, 2)
void gemm_kernel(const int* __restrict__ targets_row,
                 float* __restrict__ out, unsigned nblocks) {
    extern __shared__ char dsm[];
    __shared__ float red_s[16];
    __shared__ int   red_c[16];

    uint32_t sb = smem_u32(dsm);
    int tid = threadIdx.x;
    int wid = tid >> 5, lid = tid & 31;
    int j0 = blockIdx.x * BN;

    int i0w = (wid >> 1) * 32, j0w = (wid & 1) * 32;

    float acc[2][4][4];
    #pragma unroll
    for (int a = 0; a < 2; a++)
        #pragma unroll
        for (int b = 0; b < 4; b++)
            #pragma unroll
            for (int c = 0; c < 4; c++) acc[a][b][c] = 0.f;

    uint32_t a_lane = (uint32_t)((lid & 15) * STRB + (lid >> 4) * 16);
    uint32_t b_lane = (uint32_t)(((lid & 7) + ((lid >> 4) & 1) * 8) * STRB + ((lid >> 3) & 1) * 16);
    uint32_t aBase = sb + (uint32_t)(i0w * STRB) + a_lane;
    uint32_t bBase = sb + (uint32_t)(j0w * STRB) + b_lane;

    unsigned* s_nn = (unsigned*)(dsm + NN_OFF);

    int arow = tid >> 3, ah = tid & 7;
    const char* Asrc = (const char*)(g_Abf + arow * DIM + ah * 8);
    const char* Bsrc = (const char*)(g_Bbf + (size_t)(j0 + arow) * DIM + ah * 8);
    uint32_t a_sdst = (uint32_t)(arow * STRB + ah * 16);

    // ---- prologue ----
    {
        s_nn[tid] = g_nonneg[(size_t)j0 * 8 + tid];   // precomputed mask, 512 words
        #pragma unroll
        for (int p = 0; p < 4; p++)
            CP_ASYNC16(sb + A_T0 + a_sdst + p * 64 * STRB, Asrc + (size_t)p * 64 * DIM * 2);
        CP_ASYNC16(sb + B_T0 + a_sdst, Bsrc);
        CP_COMMIT();
        CP_WAIT0();
        __syncthreads();
    }

    // ---- mainloop ----
    #pragma unroll 2
    for (int kt = 0; kt < NCHUNK; kt++) {
        int buf = kt & 1;
        uint32_t Ab = aBase + (buf ? A_T1 : A_T0);
        uint32_t Bb = bBase + (buf ? B_T1 : B_T0);

        if (kt < NCHUNK - 1) {
            uint32_t AbN = sb + (buf ? A_T0 : A_T1);
            uint32_t BbN = sb + (buf ? B_T0 : B_T1);
            size_t kc = (size_t)(kt + 1) * BKC * 2;
            #pragma unroll
            for (int p = 0; p < 4; p++)
                CP_ASYNC16(AbN + a_sdst + p * 64 * STRB, Asrc + (size_t)p * 64 * DIM * 2 + kc);
            CP_ASYNC16(BbN + a_sdst, Bsrc + kc);
            CP_COMMIT();
        }

        #pragma unroll
        for (int ks = 0; ks < BKC; ks += 16) {
            uint32_t afr[2][4], bfr[2][4];
            #pragma unroll
            for (int mt = 0; mt < 2; mt++)
                ldsm_x4(afr[mt], Ab + (uint32_t)(mt * 16 * STRB + ks * 2));
            #pragma unroll
            for (int np = 0; np < 2; np++)
                ldsm_x4(bfr[np], Bb + (uint32_t)(np * 16 * STRB + ks * 2));
            #pragma unroll
            for (int mt = 0; mt < 2; mt++) {
                #pragma unroll
                for (int np = 0; np < 2; np++) {
                    mma16816(acc[mt][np * 2 + 0], afr[mt], bfr[np][0], bfr[np][1]);
                    mma16816(acc[mt][np * 2 + 1], afr[mt], bfr[np][2], bfr[np][3]);
                }
            }
        }

        if (kt < NCHUNK - 1) CP_WAIT0();
        __syncthreads();
    }

    // ---- epilogue tables (overlay stage A_T0) ----
    float* s_th  = (float*)(dsm + T_TH);
    float* s_na  = (float*)(dsm + T_NA);
    float* s_sa  = (float*)(dsm + T_SA);
    float* s_dap = (float*)(dsm + T_DAP);
    float* s_nb  = (float*)(dsm + T_NB);
    float* s_sb  = (float*)(dsm + T_SB);

    if (tid < 256) {
        s_th[tid]  = g_thresh[tid];
        s_na[tid]  = g_na[tid];
        s_sa[tid]  = g_sa[tid];
        s_dap[tid] = g_dap[tid];
    }
    if (tid < BN) {
        s_nb[tid] = g_nb[j0 + tid];
        s_sb[tid] = g_sb[j0 + tid];
    }
    __syncthreads();

    const float cterm = (float)DIM * EPS_F * EPS_F;
    float sumtl = 0.f;
    int cnt = 0;
    #pragma unroll
    for (int mt = 0; mt < 2; mt++) {
        int i1 = i0w + mt * 16 + (lid >> 2);
        int i2 = i1 + 8;
        float th1 = s_th[i1], na1 = s_na[i1], sa1 = s_sa[i1], dp1 = s_dap[i1];
        float th2 = s_th[i2], na2 = s_na[i2], sa2 = s_sa[i2], dp2 = s_dap[i2];
        int g1 = i1 >> 5, g2 = i2 >> 5;
        unsigned bit1 = 1u << (i1 & 31), bit2 = 1u << (i2 & 31);
        #pragma unroll
        for (int nt = 0; nt < 4; nt++) {
            int jl = j0w + nt * 8 + (lid & 3) * 2;
            #pragma unroll
            for (int c = 0; c < 4; c++) {
                int jj = jl + (c & 1);
                float s = acc[mt][nt][c];
                float th  = (c < 2) ? th1 : th2;
                unsigned bit = (c < 2) ? bit1 : bit2;
                int g = (c < 2) ? g1 : g2;
                if (s > th && !(s_nn[jj * 8 + g] & bit)) {
                    float na = (c < 2) ? na1 : na2;
                    float sa = (c < 2) ? sa1 : sa2;
                    float dp = (c < 2) ? dp1 : dp2;
                    cnt++;
                    float dan2 = na + s_nb[jj] - 2.0f * s
                               + 2.0f * EPS_F * (sa - s_sb[jj]) + cterm;
                    float dan = sqrtf(fmaxf(dan2, 0.0f));
                    float tl = dp - dan + TMARGIN_F;
                    if (tl > 0.0f) sumtl += tl;
                }
            }
        }
    }
    sumtl = warpReduceSum(sumtl);
    cnt   = warpReduceSumI(cnt);
    if (lid == 0) { red_s[wid] = sumtl; red_c[wid] = cnt; }
    __syncthreads();
    if (tid == 0) {
        float ts = 0.f; int tc = 0;
        #pragma unroll
        for (int w = 0; w < 16; w++) { ts += red_s[w]; tc += red_c[w]; }
        if (tc > 0) { atomicAdd(&g_total, (double)ts); atomicAdd(&g_count, tc); }
        __threadfence();
        unsigned d = atomicAdd(&g_done, 1u);
        if (d == nblocks - 1) {
            g_done = 0;
            __threadfence();
            int c = g_count;
            out[0] = (c > 0) ? (float)(g_total / (double)c) : 0.0f;
        }
    }
}

extern "C" void kernel_launch(void* const* d_in, const int* in_sizes, int n_in,
                              void* d_out, int out_size) {
    const float* inputs_col  = (const float*)d_in[0];
    const float* inputs_row  = (const float*)d_in[1];
    const int*   targets_col = (const int*)d_in[2];
    const int*   targets_row = (const int*)d_in[3];
    const int*   qidxs       = (const int*)d_in[4];
    // d_in[5] = pidxs: dead in the reference loss
    const int*   nnegs       = (const int*)d_in[6];

    cudaFuncSetAttribute(gemm_kernel, cudaFuncAttributeMaxDynamicSharedMemorySize, SMEM_DYN);

    prep_kernel<<<CONV_BLOCKS + BSZ, 256>>>(inputs_col, inputs_row, targets_col,
                                            qidxs, nnegs);
    mask_kernel<<<NTILE, 256>>>(targets_row);
    gemm_kernel<<<NTILE, 512, SMEM_DYN>>>(targets_row, (float*)d_out, NTILE);
}